// round 17
// baseline (speedup 1.0000x reference)
#include <cuda_runtime.h>

#define N_FFT   2048
#define L_SIG   1024
#define H_DIM   512
#define THREADS 128
#define TWO_PI  6.28318530717958647693f

// bank-conflict padding: one extra float2 per 16
#define PAD(i) ((i) + ((i) >> 4))
#define BUF_ELEMS (N_FFT + (N_FFT >> 4))   // 2176 float2 = 17.4 KB

__device__ float2 g_kf[H_DIM * N_FFT];   // 8 MB k-spectrum scratch

__device__ __forceinline__ float2 cadd(float2 a, float2 b){ return make_float2(a.x+b.x, a.y+b.y); }
__device__ __forceinline__ float2 csub(float2 a, float2 b){ return make_float2(a.x-b.x, a.y-b.y); }
__device__ __forceinline__ float2 cmul(float2 a, float2 b){
    return make_float2(a.x*b.x - a.y*b.y, a.x*b.y + a.y*b.x);
}
__device__ __forceinline__ float2 mul_negi(float2 a){ return make_float2(a.y, -a.x); } // a * (-i)

// slot map after the in-place pointwise: logical spectrum index m lives at v[HM(m)]
__device__ __forceinline__ constexpr int HM(int m){ return (m & 1) ? 8 + (m >> 1) : (m >> 1); }

__device__ __forceinline__ void dft4(float2& x0, float2& x1, float2& x2, float2& x3){
    float2 t0 = cadd(x0,x2), t1 = csub(x0,x2);
    float2 t2 = cadd(x1,x3), t3 = csub(x1,x3);
    float2 it3 = mul_negi(t3);
    x0 = cadd(t0,t2);
    x1 = cadd(t1,it3);
    x2 = csub(t0,t2);
    x3 = csub(t1,it3);
}

// 8-point DFT, natural order in/out
__device__ __forceinline__ void dft8(float2 v[8]){
    const float c = 0.70710678118654752440f;
    float2 e0=v[0], e1=v[2], e2=v[4], e3=v[6];
    float2 o0=v[1], o1=v[3], o2=v[5], o3=v[7];
    dft4(e0,e1,e2,e3);
    dft4(o0,o1,o2,o3);
    float2 w1o = make_float2(c*(o1.x + o1.y), c*(o1.y - o1.x));   // o1 * W8^1
    float2 w2o = mul_negi(o2);                                    // o2 * W8^2
    float2 w3o = make_float2(c*(o3.y - o3.x), -c*(o3.x + o3.y));  // o3 * W8^3
    v[0]=cadd(e0,o0);  v[4]=csub(e0,o0);
    v[1]=cadd(e1,w1o); v[5]=csub(e1,w1o);
    v[2]=cadd(e2,w2o); v[6]=csub(e2,w2o);
    v[3]=cadd(e3,w3o); v[7]=csub(e3,w3o);
}

// 8-point DFT computing only outputs p=0..3 (into v[0..3])
__device__ __forceinline__ void dft8_half(float2 v[8]){
    const float c = 0.70710678118654752440f;
    float2 e0=v[0], e1=v[2], e2=v[4], e3=v[6];
    float2 o0=v[1], o1=v[3], o2=v[5], o3=v[7];
    dft4(e0,e1,e2,e3);
    dft4(o0,o1,o2,o3);
    float2 w1o = make_float2(c*(o1.x + o1.y), c*(o1.y - o1.x));
    float2 w2o = mul_negi(o2);
    float2 w3o = make_float2(c*(o3.y - o3.x), -c*(o3.x + o3.y));
    v[0]=cadd(e0,o0);
    v[1]=cadd(e1,w1o);
    v[2]=cadd(e2,w2o);
    v[3]=cadd(e3,w3o);
}

// 16-point DFT as 4x4. Logical input index m is read from v[PERM ? HM(m) : m].
// OUTPUT PERMUTED: X[q + 4r] ends up in logical slot 4q + r (same mapping applied).
// If ZP, logical inputs 8..15 are treated as zero (not read).
#define SLOT16(p) (4*((p)&3) + ((p)>>2))
template<bool ZP, bool PERM>
__device__ __forceinline__ void dft16(float2 v[16]){
    const float c1 = 0.92387953251128675613f; // cos(pi/8)
    const float s1 = 0.38268343236508977173f; // sin(pi/8)
    const float r2 = 0.70710678118654752440f;
#define VV(m) v[PERM ? HM(m) : (m)]
    #pragma unroll
    for (int b = 0; b < 4; b++){
        if (ZP) {
            float2 t0 = VV(b), t1 = VV(b+4);
            VV(b)    = cadd(t0,t1);
            VV(b+4)  = make_float2(t0.x + t1.y, t0.y - t1.x); // t0 - i*t1
            VV(b+8)  = csub(t0,t1);
            VV(b+12) = make_float2(t0.x - t1.y, t0.y + t1.x); // t0 + i*t1
        } else {
            dft4(VV(b), VV(b+4), VV(b+8), VV(b+12));
        }
    }
    VV(5)  = cmul(VV(5),  make_float2(c1, -s1));   // W16^1
    VV(9)  = cmul(VV(9),  make_float2(r2, -r2));   // W16^2
    VV(13) = cmul(VV(13), make_float2(s1, -c1));   // W16^3
    VV(6)  = cmul(VV(6),  make_float2(r2, -r2));   // W16^2
    VV(10) = mul_negi(VV(10));                     // W16^4
    VV(14) = cmul(VV(14), make_float2(-r2, -r2));  // W16^6
    VV(7)  = cmul(VV(7),  make_float2(s1, -c1));   // W16^3
    VV(11) = cmul(VV(11), make_float2(-r2, -r2));  // W16^6
    VV(15) = cmul(VV(15), make_float2(-c1, s1));   // W16^9
    #pragma unroll
    for (int q = 0; q < 4; q++)
        dft4(VV(4*q), VV(4*q+1), VV(4*q+2), VV(4*q+3));
#undef VV
}

// Passes A and B of the 2048-pt radix 16*16*8 Stockham (128 thr, 16 regs).
// Logical input: x[tid + 128*m] at v-slot (PERM ? HM(m) : m).
// Leaves pass-B result in buf; ends with a __syncthreads.
template<bool ZPAD, bool PERM>
__device__ __forceinline__ void fft_AB(float2* buf, float2 v[16], int tid){
    // ---- pass A: R=16, L=1 (no twiddles)
    dft16<ZPAD, PERM>(v);
    {
        int base = tid << 4;
        #pragma unroll
        for (int p = 0; p < 16; p++)
            buf[PAD(base + p)] = v[PERM ? HM(SLOT16(p)) : SLOT16(p)];
    }
    __syncthreads();
    // ---- pass B: R=16, L=16 (natural slots from here on)
    #pragma unroll
    for (int m = 0; m < 16; m++) v[m] = buf[PAD(tid + (m<<7))];
    __syncthreads();
    {
        int k = tid & 15;
        float s, c; __sincosf(-(float)k * (TWO_PI/256.f), &s, &c);
        float2 w1 = make_float2(c, s);
        // two interleaved power chains stepping by w2: depth 14 -> 7
        float2 w2 = cmul(w1, w1);
        float2 a = w1, b = w2;
        v[1]  = cmul(v[1],  a);  v[2]  = cmul(v[2],  b);
        a = cmul(a, w2); v[3]  = cmul(v[3],  a);
        b = cmul(b, w2); v[4]  = cmul(v[4],  b);
        a = cmul(a, w2); v[5]  = cmul(v[5],  a);
        b = cmul(b, w2); v[6]  = cmul(v[6],  b);
        a = cmul(a, w2); v[7]  = cmul(v[7],  a);
        b = cmul(b, w2); v[8]  = cmul(v[8],  b);
        a = cmul(a, w2); v[9]  = cmul(v[9],  a);
        b = cmul(b, w2); v[10] = cmul(v[10], b);
        a = cmul(a, w2); v[11] = cmul(v[11], a);
        b = cmul(b, w2); v[12] = cmul(v[12], b);
        a = cmul(a, w2); v[13] = cmul(v[13], a);
        b = cmul(b, w2); v[14] = cmul(v[14], b);
        a = cmul(a, w2); v[15] = cmul(v[15], a);
        dft16<false, false>(v);
        int base = ((tid >> 4) << 8) + k;
        #pragma unroll
        for (int p = 0; p < 16; p++)
            buf[PAD(base + (p<<4))] = v[SLOT16(p)];
    }
    __syncthreads();
}

// Pass C loads: v[0..7] <- butterfly at t=tid, v[8..15] <- t=tid+128
__device__ __forceinline__ void passC_load(const float2* buf, float2 v[16], int tid){
    #pragma unroll
    for (int m = 0; m < 8; m++) v[m]     = buf[PAD(tid       + (m<<8))];
    #pragma unroll
    for (int m = 0; m < 8; m++) v[8 + m] = buf[PAD(tid + 128 + (m<<8))];
}

// Pass C twiddle for butterfly index t: v[m] *= W2048^{t*m}
// Two interleaved chains stepping by w2: depth 6 -> 4.
__device__ __forceinline__ void passC_twiddle(float2 v[8], int t){
    float s, c;
    __sincosf(-(float)t * (TWO_PI/2048.f), &s, &c);
    float2 w1 = make_float2(c, s);
    float2 w2 = cmul(w1, w1);
    float2 a = w1, b = w2;
    v[1] = cmul(v[1], a);  v[2] = cmul(v[2], b);
    a = cmul(a, w2); v[3] = cmul(v[3], a);
    b = cmul(b, w2); v[4] = cmul(v[4], b);
    a = cmul(a, w2); v[5] = cmul(v[5], a);
    b = cmul(b, w2); v[6] = cmul(v[6], b);
    a = cmul(a, w2); v[7] = cmul(v[7], a);
}

// One block per h: spectrum of zero-padded k row -> g_kf[h].
// Fires the PDL trigger at entry so conv_kernel can launch and overlap its
// forward FFT with this kernel; conv's griddepsync waits for our completion.
__global__ void __launch_bounds__(THREADS, 4) kf_kernel(const float* __restrict__ k) {
    cudaTriggerProgrammaticLaunchCompletion();
    __shared__ float2 buf[BUF_ELEMS];
    const int h = blockIdx.x;
    const int tid = threadIdx.x;
    const float* kr = k + (size_t)h * L_SIG;
    float2 v[16];
    #pragma unroll
    for (int m = 0; m < 8; m++) v[m] = make_float2(kr[tid + (m<<7)], 0.0f);

    fft_AB<true, false>(buf, v, tid);
    passC_load(buf, v, tid);
    passC_twiddle(v, tid);           dft8(v);
    passC_twiddle(v + 8, tid + 128); dft8(v + 8);

    float2* dst = g_kf + (size_t)h * N_FFT;
    #pragma unroll
    for (int p = 0; p < 8; p++) {
        dst[tid       + (p<<8)] = v[p];
        dst[tid + 128 + (p<<8)] = v[8 + p];
    }
}

// One block per (h, batch-pair). z = u_b + i*u_{b+1}; IFFT(FFT(z)*K) = y_b + i*y_{b+1}
// (k real). IFFT(v) = conj(FFT(conj(v)))/N: FFT conj(z_f*K), read Re / -Im.
// PDL: this kernel launches while kf_kernel is still running; the u prefetch and
// the whole forward passes A/B overlap with kf. cudaGridDependencySynchronize()
// (= wait for kf completion) sits right before the kbuf cp.async, one FFT pass
// ahead of the pointwise, so the kf spectrum load latency stays hidden.
__global__ void __launch_bounds__(THREADS, 4) conv_kernel(const float* __restrict__ u,
                                                          const float* __restrict__ D,
                                                          float* __restrict__ out) {
    __shared__ float2 buf[BUF_ELEMS];
    __shared__ float2 kbuf[N_FFT];          // 16 KB prefetched spectrum
    __shared__ float  ubuf[2 * L_SIG];      // 8 KB prefetched u rows (epilogue)
    const int h   = blockIdx.x;   // 0..511
    const int bp  = blockIdx.y;   // 0..7
    const int tid = threadIdx.x;

    const size_t row_stride = (size_t)H_DIM * L_SIG;
    const float* u0 = u + ((size_t)(2 * bp) * H_DIM + h) * L_SIG;
    const float* u1 = u0 + row_stride;

    // ---- async prefetch of u rows for the epilogue (independent of kf)
    {
        unsigned ub = (unsigned)__cvta_generic_to_shared(ubuf);
        #pragma unroll
        for (int r = 0; r < 2; r++) {
            int c = tid + (r<<7);            // 16B chunk index, 0..255
            asm volatile("cp.async.cg.shared.global [%0], [%1], 16;"
                         :: "r"(ub + c*16), "l"(u0 + c*4));
            asm volatile("cp.async.cg.shared.global [%0], [%1], 16;"
                         :: "r"(ub + 4096 + c*16), "l"(u1 + c*4));
        }
        asm volatile("cp.async.commit_group;");
    }

    float2 v[16];
    #pragma unroll
    for (int m = 0; m < 8; m++) {
        int idx = tid + (m<<7);
        v[m] = make_float2(u0[idx], u1[idx]);
    }

    // ---- forward FFT passes A,B (overlaps with kf_kernel under PDL)
    fft_AB<true, false>(buf, v, tid);

    // ---- kf is needed one pass from now: wait for kf_kernel completion, then
    //      prefetch K_h into smem (8 x 16B per thread).
    cudaGridDependencySynchronize();
    {
        const float2* __restrict__ src = g_kf + (size_t)h * N_FFT;
        unsigned kb = (unsigned)__cvta_generic_to_shared(kbuf);
        #pragma unroll
        for (int r = 0; r < 8; r++) {
            int c = tid + (r<<7);            // 16B chunk index, 0..1023
            asm volatile("cp.async.cg.shared.global [%0], [%1], 16;"
                         :: "r"(kb + c*16), "l"(src + c*2));
        }
        asm volatile("cp.async.commit_group;");
    }

    // ---- forward pass C in registers
    passC_load(buf, v, tid);
    passC_twiddle(v, tid);           dft8(v);
    passC_twiddle(v + 8, tid + 128); dft8(v + 8);

    // ---- make async copies (kbuf + ubuf) visible to ALL threads, and order
    //      all fwd buf reads before inverse pass-A writes: wait + barrier.
    asm volatile("cp.async.wait_group 0;");
    __syncthreads();

    // ---- fused pointwise IN PLACE from smem kbuf: v[p] holds Z[tid+256p],
    //      v[8+p] holds Z[tid+128+256p]. Afterwards logical spectrum index m
    //      sits at slot HM(m). Conflict-free LDS (consecutive lanes).
    #pragma unroll
    for (int p = 0; p < 8; p++) {
        float2 K0 = kbuf[tid       + (p<<8)];
        float2 z0 = v[p];
        v[p]     = make_float2(z0.x*K0.x - z0.y*K0.y, -(z0.x*K0.y + z0.y*K0.x));
        float2 K1 = kbuf[tid + 128 + (p<<8)];
        float2 z1 = v[8 + p];
        v[8 + p] = make_float2(z1.x*K1.x - z1.y*K1.y, -(z1.x*K1.y + z1.y*K1.x));
    }

    // ---- inverse FFT: pass A reads through HM, passes B/C natural, truncated
    fft_AB<false, true>(buf, v, tid);
    passC_load(buf, v, tid);
    passC_twiddle(v, tid);           dft8_half(v);
    passC_twiddle(v + 8, tid + 128); dft8_half(v + 8);

    // ---- epilogue: y direct from registers; skip term u*D from smem ubuf
    const float d   = D[h];
    const float inv = 1.0f / (float)N_FFT;
    float* y0 = out + ((size_t)(2 * bp) * H_DIM + h) * L_SIG;
    float* y1 = y0 + row_stride;
    #pragma unroll
    for (int p = 0; p < 4; p++) {
        int i0 = tid + (p<<8);
        int i1 = tid + 128 + (p<<8);
        float2 r0 = v[p];
        float2 r1 = v[8 + p];
        y0[i0] =  r0.x * inv + ubuf[i0] * d;
        y1[i0] = -r0.y * inv + ubuf[L_SIG + i0] * d;
        y0[i1] =  r1.x * inv + ubuf[i1] * d;
        y1[i1] = -r1.y * inv + ubuf[L_SIG + i1] * d;
    }
}

extern "C" void kernel_launch(void* const* d_in, const int* in_sizes, int n_in,
                              void* d_out, int out_size) {
    const float* u = (const float*)d_in[0];
    const float* k = (const float*)d_in[1];
    const float* D = (const float*)d_in[2];
    float* out = (float*)d_out;

    kf_kernel<<<H_DIM, THREADS>>>(k);

    // conv with Programmatic Dependent Launch: may begin while kf is running;
    // its griddepsync provides the g_kf dependency.
    cudaLaunchConfig_t cfg = {};
    cfg.gridDim  = dim3(H_DIM, 8);
    cfg.blockDim = dim3(THREADS);
    cfg.dynamicSmemBytes = 0;
    cfg.stream = 0;   // legacy default stream (captured by the harness)
    cudaLaunchAttribute attrs[1];
    attrs[0].id = cudaLaunchAttributeProgrammaticStreamSerialization;
    attrs[0].val.programmaticStreamSerializationAllowed = 1;
    cfg.attrs = attrs;
    cfg.numAttrs = 1;
    cudaLaunchKernelEx(&cfg, conv_kernel, u, D, out);
}